// round 9
// baseline (speedup 1.0000x reference)
#include <cuda_runtime.h>

#define CH 512
#define LOG2E 1.4426950408889634f
#define NINT 20          // interpolation intervals
#define NNODE 23         // nodes: j=0..22, node j at s = qmin + (j-1)*h

__device__ __forceinline__ float ex2(float x) {
    float r;
    asm("ex2.approx.ftz.f32 %0, %1;" : "=f"(r) : "f"(x));
    return r;
}

// grid 256 (one batch/CTA), block 512 (one channel/thread)
__global__ __launch_bounds__(512) void attn1d_kernel(
    const float* __restrict__ q, const float* __restrict__ k, const float* __restrict__ v,
    const float* __restrict__ wq, const float* __restrict__ wk, const float* __restrict__ wv,
    float* __restrict__ out)
{
    __shared__ float sq[CH + 4], sk[CH + 4], sv[CH + 4];
    __shared__ __align__(16) float skh[CH];   // khL = kh * log2e
    __shared__ __align__(16) float svv[CH];   // vh
    __shared__ float red[32];                 // 16 warps x {qmax, qmin}
    __shared__ float Rarr[NNODE + 1];

    const int b = blockIdx.x;
    const int t = threadIdx.x;
    const int warp = t >> 5, lane = t & 31;

    const float* qb = q + b * CH;
    const float* kb = k + b * CH;
    const float* vb = v + b * CH;

    if (t < 4) {
        const int i = (t < 2) ? t : (CH + t);  // 0,1,CH+2,CH+3
        sq[i] = 0.f; sk[i] = 0.f; sv[i] = 0.f;
    }
    sq[t + 2] = qb[t];
    sk[t + 2] = kb[t];
    sv[t + 2] = vb[t];

    float Wq[5], Wk[5], Wv[5];
    #pragma unroll
    for (int j = 0; j < 5; j++) { Wq[j] = wq[j]; Wk[j] = wk[j]; Wv[j] = wv[j]; }

    __syncthreads();

    // conv: one channel per thread
    float kh = 0.f, vh = 0.f, s = 0.f;
    #pragma unroll
    for (int j = 0; j < 5; j++) {
        kh = fmaf(Wk[j], sk[t + j], kh);
        vh = fmaf(Wv[j], sv[t + j], vh);
        s  = fmaf(Wq[j], sq[t + j], s);
    }
    skh[t] = kh * LOG2E;
    svv[t] = vh;

    float qmaxl = s, qminl = s;
    #pragma unroll
    for (int o = 16; o; o >>= 1) {
        qmaxl = fmaxf(qmaxl, __shfl_xor_sync(0xffffffffu, qmaxl, o));
        qminl = fminf(qminl, __shfl_xor_sync(0xffffffffu, qminl, o));
    }
    if (lane == 0) {
        red[warp * 2 + 0] = qmaxl;
        red[warp * 2 + 1] = qminl;
    }
    __syncthreads();   // also publishes skh/svv

    float qmax = red[0], qmin = red[1];
    #pragma unroll
    for (int i = 1; i < 16; i++) {
        qmax = fmaxf(qmax, red[i * 2 + 0]);
        qmin = fminf(qmin, red[i * 2 + 1]);
    }

    const float range = qmax - qmin;
    const bool  degen = !(range > 1e-30f);
    const float h     = degen ? 1.f : range * (1.f / NINT);
    const float inv_h = degen ? 0.f : (float)NINT / range;

    // ── node stage: warps 0..15 own node `warp`; warps 0..6 also own node warp+16 ──
    // no max-subtraction: |s*khL| small, exp2 in fp32 range; ratio shift-invariant.
    const float4* skh4 = (const float4*)skh;
    const float4* svv4 = (const float4*)svv;

    const int  j1      = warp + 16;
    const bool active1 = (j1 < NNODE);
    const float sj0 = fmaf((float)(warp - 1), h, qmin);
    const float sj1 = fmaf((float)(j1 - 1), h, qmin);

    float num0 = 0.f, den0 = 0.f, num1 = 0.f, den1 = 0.f;

    #pragma unroll
    for (int c4 = 0; c4 < 4; c4++) {
        const float4 xk = skh4[lane + 32 * c4];   // LDS.128, reused for both nodes
        const float4 xv = svv4[lane + 32 * c4];
        {
            const float e0 = ex2(sj0 * xk.x);
            const float e1 = ex2(sj0 * xk.y);
            const float e2 = ex2(sj0 * xk.z);
            const float e3 = ex2(sj0 * xk.w);
            num0 = fmaf(e0, xv.x, num0); den0 += e0;
            num0 = fmaf(e1, xv.y, num0); den0 += e1;
            num0 = fmaf(e2, xv.z, num0); den0 += e2;
            num0 = fmaf(e3, xv.w, num0); den0 += e3;
        }
        if (active1) {                             // warp-uniform branch
            const float e0 = ex2(sj1 * xk.x);
            const float e1 = ex2(sj1 * xk.y);
            const float e2 = ex2(sj1 * xk.z);
            const float e3 = ex2(sj1 * xk.w);
            num1 = fmaf(e0, xv.x, num1); den1 += e0;
            num1 = fmaf(e1, xv.y, num1); den1 += e1;
            num1 = fmaf(e2, xv.z, num1); den1 += e2;
            num1 = fmaf(e3, xv.w, num1); den1 += e3;
        }
    }

    #pragma unroll
    for (int o = 16; o; o >>= 1) {
        num0 += __shfl_xor_sync(0xffffffffu, num0, o);
        den0 += __shfl_xor_sync(0xffffffffu, den0, o);
        num1 += __shfl_xor_sync(0xffffffffu, num1, o);
        den1 += __shfl_xor_sync(0xffffffffu, den1, o);
    }
    if (lane == 0) {
        Rarr[warp] = __fdividef(num0, den0);
        if (active1) Rarr[j1] = __fdividef(num1, den1);
    }
    __syncthreads();

    // ── eval stage: cubic Lagrange through 4 nearest nodes ──
    {
        float u = (s - qmin) * inv_h;
        u = fminf(fmaxf(u, 0.f), (float)NINT);
        int i = (int)u;
        i = min(i, NINT - 1);
        const float p = u - (float)i;          // in [0,1]
        // nodes at relative positions -1,0,1,2 -> Rarr[i..i+3]
        const float pm1 = p - 1.f, pm2 = p - 2.f, pp1 = p + 1.f;
        const float wm1 = -p * pm1 * pm2 * (1.f / 6.f);
        const float w0  =  pp1 * pm1 * pm2 * 0.5f;
        const float w1  = -pp1 * p * pm2 * 0.5f;
        const float w2  =  pp1 * p * pm1 * (1.f / 6.f);
        out[b * CH + t] = wm1 * Rarr[i] + w0 * Rarr[i + 1]
                        + w1 * Rarr[i + 2] + w2 * Rarr[i + 3];
    }
}

extern "C" void kernel_launch(void* const* d_in, const int* in_sizes, int n_in,
                              void* d_out, int out_size) {
    const float* q  = (const float*)d_in[0];
    const float* k  = (const float*)d_in[1];
    const float* v  = (const float*)d_in[2];
    const float* wq = (const float*)d_in[3];
    const float* wk = (const float*)d_in[4];
    const float* wv = (const float*)d_in[5];
    float* out = (float*)d_out;
    attn1d_kernel<<<256, 512>>>(q, k, v, wq, wk, wv, out);
}

// round 10
// speedup vs baseline: 1.1723x; 1.1723x over previous
#include <cuda_runtime.h>

#define CH 512
#define LOG2E 1.4426950408889634f
#define NINT 20          // interpolation intervals
#define NNODE 23         // nodes: j=0..22, node j at s = qmin + (j-1)*h

__device__ __forceinline__ float ex2(float x) {
    float r;
    asm("ex2.approx.ftz.f32 %0, %1;" : "=f"(r) : "f"(x));
    return r;
}

// grid 128 (two batches/CTA), block 256
__global__ __launch_bounds__(256) void attn1d_kernel(
    const float* __restrict__ q, const float* __restrict__ k, const float* __restrict__ v,
    const float* __restrict__ wq, const float* __restrict__ wk, const float* __restrict__ wv,
    float* __restrict__ out)
{
    __shared__ float sq[2][CH + 4], sk[2][CH + 4], sv[2][CH + 4];
    __shared__ __align__(16) float skh[2][CH];   // khL = kh * log2e
    __shared__ __align__(16) float svv[2][CH];   // vh
    __shared__ float red[32];                    // 8 warps x {qmax0, qmin0, qmax1, qmin1}
    __shared__ float Rarr[2][NNODE + 1];

    const int b0 = blockIdx.x * 2;
    const int t  = threadIdx.x;
    const int warp = t >> 5, lane = t & 31;

    // float2 row loads: thread t covers channels 2t, 2t+1 of each tensor, both batches
    const float2* q2[2] = { (const float2*)(q + b0 * CH), (const float2*)(q + (b0 + 1) * CH) };
    const float2* k2[2] = { (const float2*)(k + b0 * CH), (const float2*)(k + (b0 + 1) * CH) };
    const float2* v2[2] = { (const float2*)(v + b0 * CH), (const float2*)(v + (b0 + 1) * CH) };

    // issue ALL gmem loads up-front (overlap latency once)
    float2 lq[2], lk[2], lv[2];
    #pragma unroll
    for (int bb = 0; bb < 2; bb++) {
        lq[bb] = q2[bb][t];
        lk[bb] = k2[bb][t];
        lv[bb] = v2[bb][t];
    }
    float Wq[5], Wk[5], Wv[5];
    #pragma unroll
    for (int j = 0; j < 5; j++) { Wq[j] = wq[j]; Wk[j] = wk[j]; Wv[j] = wv[j]; }

    #pragma unroll
    for (int bb = 0; bb < 2; bb++) {
        if (t < 4) {
            const int i = (t < 2) ? t : (CH + t);  // 0,1,CH+2,CH+3
            sq[bb][i] = 0.f; sk[bb][i] = 0.f; sv[bb][i] = 0.f;
        }
        // channel c -> index c+2 ; 2t+2 is 8B-aligned
        *(float2*)&sq[bb][2 * t + 2] = lq[bb];
        *(float2*)&sk[bb][2 * t + 2] = lk[bb];
        *(float2*)&sv[bb][2 * t + 2] = lv[bb];
    }
    __syncthreads();

    // convs: each thread does channels t and t+256, both batches
    float qmaxl[2], qminl[2], s0[2], s1[2];
    #pragma unroll
    for (int bb = 0; bb < 2; bb++) {
        qmaxl[bb] = -1e30f; qminl[bb] = 1e30f;
        #pragma unroll
        for (int h2 = 0; h2 < 2; h2++) {
            const int c = t + h2 * 256;
            float kh = 0.f, vh = 0.f, qh = 0.f;
            #pragma unroll
            for (int j = 0; j < 5; j++) {
                kh = fmaf(Wk[j], sk[bb][c + j], kh);
                vh = fmaf(Wv[j], sv[bb][c + j], vh);
                qh = fmaf(Wq[j], sq[bb][c + j], qh);
            }
            skh[bb][c] = kh * LOG2E;
            svv[bb][c] = vh;
            qmaxl[bb] = fmaxf(qmaxl[bb], qh);
            qminl[bb] = fminf(qminl[bb], qh);
            if (h2 == 0) s0[bb] = qh; else s1[bb] = qh;
        }
    }

    #pragma unroll
    for (int o = 16; o; o >>= 1) {
        #pragma unroll
        for (int bb = 0; bb < 2; bb++) {
            qmaxl[bb] = fmaxf(qmaxl[bb], __shfl_xor_sync(0xffffffffu, qmaxl[bb], o));
            qminl[bb] = fminf(qminl[bb], __shfl_xor_sync(0xffffffffu, qminl[bb], o));
        }
    }
    if (lane == 0) {
        red[warp * 4 + 0] = qmaxl[0];
        red[warp * 4 + 1] = qminl[0];
        red[warp * 4 + 2] = qmaxl[1];
        red[warp * 4 + 3] = qminl[1];
    }
    __syncthreads();   // also publishes skh/svv

    float qmax[2], qmin[2];
    qmax[0] = red[0]; qmin[0] = red[1]; qmax[1] = red[2]; qmin[1] = red[3];
    #pragma unroll
    for (int i = 1; i < 8; i++) {
        qmax[0] = fmaxf(qmax[0], red[i * 4 + 0]);
        qmin[0] = fminf(qmin[0], red[i * 4 + 1]);
        qmax[1] = fmaxf(qmax[1], red[i * 4 + 2]);
        qmin[1] = fminf(qmin[1], red[i * 4 + 3]);
    }

    float h[2], inv_h[2];
    #pragma unroll
    for (int bb = 0; bb < 2; bb++) {
        const float range = qmax[bb] - qmin[bb];
        const bool  degen = !(range > 1e-30f);
        h[bb]     = degen ? 1.f : range * (1.f / NINT);
        inv_h[bb] = degen ? 0.f : (float)NINT / range;
    }

    // ── node stage: each warp owns nodes {w, w+8, w+16} for BOTH batches ──
    // no max-subtraction: |s*khL| small, exp2 in fp32 range; ratio shift-invariant.
    float sj[2][3], num[2][3], den[2][3];
    #pragma unroll
    for (int bb = 0; bb < 2; bb++)
        #pragma unroll
        for (int i = 0; i < 3; i++) {
            const int j = warp + 8 * i;      // j=23 (warp7,i=2) computed, not stored
            sj[bb][i] = fmaf((float)(j - 1), h[bb], qmin[bb]);
            num[bb][i] = 0.f; den[bb][i] = 0.f;
        }

    #pragma unroll
    for (int c4 = 0; c4 < 4; c4++) {
        #pragma unroll
        for (int bb = 0; bb < 2; bb++) {
            const float4 xk = ((const float4*)skh[bb])[lane + 32 * c4];
            const float4 xv = ((const float4*)svv[bb])[lane + 32 * c4];
            #pragma unroll
            for (int i = 0; i < 3; i++) {
                const float e0 = ex2(sj[bb][i] * xk.x);
                const float e1 = ex2(sj[bb][i] * xk.y);
                const float e2 = ex2(sj[bb][i] * xk.z);
                const float e3 = ex2(sj[bb][i] * xk.w);
                num[bb][i] = fmaf(e0, xv.x, num[bb][i]); den[bb][i] += e0;
                num[bb][i] = fmaf(e1, xv.y, num[bb][i]); den[bb][i] += e1;
                num[bb][i] = fmaf(e2, xv.z, num[bb][i]); den[bb][i] += e2;
                num[bb][i] = fmaf(e3, xv.w, num[bb][i]); den[bb][i] += e3;
            }
        }
    }

    // 12 independent butterfly reductions, pipelined through the SHFL unit
    #pragma unroll
    for (int o = 16; o; o >>= 1) {
        #pragma unroll
        for (int bb = 0; bb < 2; bb++)
            #pragma unroll
            for (int i = 0; i < 3; i++) {
                num[bb][i] += __shfl_xor_sync(0xffffffffu, num[bb][i], o);
                den[bb][i] += __shfl_xor_sync(0xffffffffu, den[bb][i], o);
            }
    }
    if (lane == 0) {
        #pragma unroll
        for (int bb = 0; bb < 2; bb++)
            #pragma unroll
            for (int i = 0; i < 3; i++) {
                const int j = warp + 8 * i;
                if (j < NNODE) Rarr[bb][j] = __fdividef(num[bb][i], den[bb][i]);
            }
    }
    __syncthreads();

    // ── eval stage: cubic Lagrange through 4 nearest nodes ──
    #pragma unroll
    for (int bb = 0; bb < 2; bb++) {
        #pragma unroll
        for (int h2 = 0; h2 < 2; h2++) {
            const float s = (h2 == 0) ? s0[bb] : s1[bb];
            float u = (s - qmin[bb]) * inv_h[bb];
            u = fminf(fmaxf(u, 0.f), (float)NINT);
            int i = (int)u;
            i = min(i, NINT - 1);
            const float p = u - (float)i;          // in [0,1]
            const float pm1 = p - 1.f, pm2 = p - 2.f, pp1 = p + 1.f;
            const float wm1 = -p * pm1 * pm2 * (1.f / 6.f);
            const float w0  =  pp1 * pm1 * pm2 * 0.5f;
            const float w1  = -pp1 * p * pm2 * 0.5f;
            const float w2  =  pp1 * p * pm1 * (1.f / 6.f);
            out[(b0 + bb) * CH + t + h2 * 256] =
                  wm1 * Rarr[bb][i] + w0 * Rarr[bb][i + 1]
                + w1 * Rarr[bb][i + 2] + w2 * Rarr[bb][i + 3];
        }
    }
}

extern "C" void kernel_launch(void* const* d_in, const int* in_sizes, int n_in,
                              void* d_out, int out_size) {
    const float* q  = (const float*)d_in[0];
    const float* k  = (const float*)d_in[1];
    const float* v  = (const float*)d_in[2];
    const float* wq = (const float*)d_in[3];
    const float* wk = (const float*)d_in[4];
    const float* wv = (const float*)d_in[5];
    float* out = (float*)d_out;
    attn1d_kernel<<<128, 256>>>(q, k, v, wq, wk, wv, out);
}

// round 11
// speedup vs baseline: 1.3478x; 1.1498x over previous
#include <cuda_runtime.h>

#define CH 512
#define LOG2E 1.4426950408889634f
#define NINT 18          // interpolation intervals
#define NNODE 21         // nodes: j=0..20, node j at s = qmin + (j-1)*h

__device__ __forceinline__ float ex2(float x) {
    float r;
    asm("ex2.approx.ftz.f32 %0, %1;" : "=f"(r) : "f"(x));
    return r;
}

// grid 256 (one batch/CTA), block 256, channels t and t+256 per thread
__global__ __launch_bounds__(256) void attn1d_kernel(
    const float* __restrict__ q, const float* __restrict__ k, const float* __restrict__ v,
    const float* __restrict__ wq, const float* __restrict__ wk, const float* __restrict__ wv,
    float* __restrict__ out)
{
    __shared__ __align__(16) float skh[CH];   // khL = kh * log2e
    __shared__ __align__(16) float svv[CH];   // vh
    __shared__ float red[16];                 // 8 warps x {qmax, qmin}
    __shared__ float Rarr[NNODE + 1];

    const int b = blockIdx.x;
    const int t = threadIdx.x;
    const int warp = t >> 5, lane = t & 31;

    const float* qb = q + b * CH;
    const float* kb = k + b * CH;
    const float* vb = v + b * CH;

    float Wq[5], Wk[5], Wv[5];
    #pragma unroll
    for (int j = 0; j < 5; j++) { Wq[j] = wq[j]; Wk[j] = wk[j]; Wv[j] = wv[j]; }

    // direct-gmem conv: no input staging, no first barrier.
    // Loads are warp-coalesced per tap; 5 taps share lines via L1.
    float qmaxl = -1e30f, qminl = 1e30f;
    float s0 = 0.f, s1 = 0.f;
    #pragma unroll
    for (int h2 = 0; h2 < 2; h2++) {
        const int c = t + h2 * 256;
        float kh = 0.f, vh = 0.f, qh = 0.f;
        #pragma unroll
        for (int j = 0; j < 5; j++) {
            const int idx = c + j - 2;
            const bool ok = (idx >= 0) && (idx < CH);
            const float qv = ok ? __ldg(qb + idx) : 0.f;
            const float kv = ok ? __ldg(kb + idx) : 0.f;
            const float vv = ok ? __ldg(vb + idx) : 0.f;
            qh = fmaf(Wq[j], qv, qh);
            kh = fmaf(Wk[j], kv, kh);
            vh = fmaf(Wv[j], vv, vh);
        }
        skh[c] = kh * LOG2E;
        svv[c] = vh;
        qmaxl = fmaxf(qmaxl, qh);
        qminl = fminf(qminl, qh);
        if (h2 == 0) s0 = qh; else s1 = qh;
    }

    #pragma unroll
    for (int o = 16; o; o >>= 1) {
        qmaxl = fmaxf(qmaxl, __shfl_xor_sync(0xffffffffu, qmaxl, o));
        qminl = fminf(qminl, __shfl_xor_sync(0xffffffffu, qminl, o));
    }
    if (lane == 0) {
        red[warp * 2 + 0] = qmaxl;
        red[warp * 2 + 1] = qminl;
    }
    __syncthreads();   // publishes skh/svv AND red (single pre-node barrier)

    float qmax = red[0], qmin = red[1];
    #pragma unroll
    for (int i = 1; i < 8; i++) {
        qmax = fmaxf(qmax, red[i * 2 + 0]);
        qmin = fminf(qmin, red[i * 2 + 1]);
    }

    const float range = qmax - qmin;
    const bool  degen = !(range > 1e-30f);
    const float h     = degen ? 1.f : range * (1.f / NINT);
    const float inv_h = degen ? 0.f : (float)NINT / range;

    // ── node stage: ONE round, warp owns nodes {w, w+8, w+16} (guarded) ──
    // no max-subtraction: |s*khL| <~ 25, exp2 stays in fp32 range;
    // num/den ratio is shift-invariant anyway.
    const float4* skh4 = (const float4*)skh;
    const float4* svv4 = (const float4*)svv;

    float sj[3], num[3], den[3];
    #pragma unroll
    for (int i = 0; i < 3; i++) {
        const int j = warp + 8 * i;            // j >= NNODE computed, not stored
        sj[i] = fmaf((float)(j - 1), h, qmin);
        num[i] = 0.f; den[i] = 0.f;
    }

    #pragma unroll
    for (int c4 = 0; c4 < 4; c4++) {
        const float4 xk = skh4[lane + 32 * c4];   // LDS.128, reused for 3 nodes
        const float4 xv = svv4[lane + 32 * c4];
        #pragma unroll
        for (int i = 0; i < 3; i++) {
            const float e0 = ex2(sj[i] * xk.x);
            const float e1 = ex2(sj[i] * xk.y);
            const float e2 = ex2(sj[i] * xk.z);
            const float e3 = ex2(sj[i] * xk.w);
            num[i] = fmaf(e0, xv.x, num[i]); den[i] += e0;
            num[i] = fmaf(e1, xv.y, num[i]); den[i] += e1;
            num[i] = fmaf(e2, xv.z, num[i]); den[i] += e2;
            num[i] = fmaf(e3, xv.w, num[i]); den[i] += e3;
        }
    }

    // 6 independent butterfly reductions, pipelined through the SHFL unit
    #pragma unroll
    for (int o = 16; o; o >>= 1) {
        #pragma unroll
        for (int i = 0; i < 3; i++) {
            num[i] += __shfl_xor_sync(0xffffffffu, num[i], o);
            den[i] += __shfl_xor_sync(0xffffffffu, den[i], o);
        }
    }
    if (lane == 0) {
        #pragma unroll
        for (int i = 0; i < 3; i++) {
            const int j = warp + 8 * i;
            if (j < NNODE) Rarr[j] = __fdividef(num[i], den[i]);
        }
    }
    __syncthreads();

    // ── eval stage: cubic Lagrange through 4 nearest nodes ──
    #pragma unroll
    for (int h2 = 0; h2 < 2; h2++) {
        const float s = (h2 == 0) ? s0 : s1;
        float u = (s - qmin) * inv_h;
        u = fminf(fmaxf(u, 0.f), (float)NINT);
        int i = (int)u;
        i = min(i, NINT - 1);
        const float p = u - (float)i;          // in [0,1]
        // nodes at relative positions -1,0,1,2 -> Rarr[i..i+3]
        const float pm1 = p - 1.f, pm2 = p - 2.f, pp1 = p + 1.f;
        const float wm1 = -p * pm1 * pm2 * (1.f / 6.f);
        const float w0  =  pp1 * pm1 * pm2 * 0.5f;
        const float w1  = -pp1 * p * pm2 * 0.5f;
        const float w2  =  pp1 * p * pm1 * (1.f / 6.f);
        out[b * CH + t + h2 * 256] = wm1 * Rarr[i] + w0 * Rarr[i + 1]
                                   + w1 * Rarr[i + 2] + w2 * Rarr[i + 3];
    }
}

extern "C" void kernel_launch(void* const* d_in, const int* in_sizes, int n_in,
                              void* d_out, int out_size) {
    const float* q  = (const float*)d_in[0];
    const float* k  = (const float*)d_in[1];
    const float* v  = (const float*)d_in[2];
    const float* wq = (const float*)d_in[3];
    const float* wk = (const float*)d_in[4];
    const float* wv = (const float*)d_in[5];
    float* out = (float*)d_out;
    attn1d_kernel<<<256, 256>>>(q, k, v, wq, wk, wv, out);
}